// round 14
// baseline (speedup 1.0000x reference)
#include <cuda_runtime.h>
#include <cstdint>
#include <math.h>

#define NP 8192            // particles == channels
#define NWB (NP / 16)      // k_weights grid size (512 blocks)

// ---------------- device scratch (no allocations allowed) ----------------
// Zero-initialized at module load; thereafter the LAST k_cat block of each
// launch resets flags/accumulators for the next launch (stream-ordered).
__device__ float g_state[NP * 3];
__device__ float g_invw[NP];
__device__ float g_sum[3];
__device__ int   g_done;
__device__ int   g_wdone;   // k_weights completion counter (software flag)

// ---------------- threefry2x32 (JAX rotation schedule) -------------------
__device__ __forceinline__ uint32_t tf32(uint32_t k0, uint32_t k1, uint32_t n)
{
    uint32_t k2 = k0 ^ k1 ^ 0x1BD11BDAu;
    uint32_t x0 = k0;          // 0 + ks[0]
    uint32_t x1 = n + k1;      // n + ks[1]
#define TFR(r) { x0 += x1; x1 = __funnelshift_l(x1, x1, (r)); x1 ^= x0; }
    TFR(13) TFR(15) TFR(26) TFR(6)
    x0 += k1; x1 += k2 + 1u;
    TFR(17) TFR(29) TFR(16) TFR(24)
    x0 += k2; x1 += k0 + 2u;
    TFR(13) TFR(15) TFR(26) TFR(6)
    x0 += k0; x1 += k1 + 3u;
    TFR(17) TFR(29) TFR(16) TFR(24)
    x0 += k1; x1 += k2 + 4u;
    TFR(13) TFR(15) TFR(26) TFR(6)
    x0 += k2; x1 += k0 + 5u;
#undef TFR
    return x0 ^ x1;
}

// exact v for the categorical: v = (-logf(u)) * invw, identical arithmetic
// to the validated round-1 kernel (bitwise-stable selection).
__device__ __forceinline__ float exact_v(uint32_t b, float invw)
{
    uint32_t tbits = __umulhi(b, 0x00800000u) + 0x3f800000u; // 1 + (b>>9)*2^-23
    float f = __uint_as_float(tbits) - 1.0f;
    float u = fmaxf(f, 1.17549435e-38f);
    float e = -logf(u);
    return e * invw;
}

// ---------------- kernel B: fused state + weights --------------------------
// Threads 0..15 compute this block's 16 particle states (identical arithmetic
// to the old k_state) into g_state + smem, then the round-9-validated weights
// loop runs. Early PDL trigger; g_wdone signals state+invw complete & fenced.
__global__ void k_weights(const float* __restrict__ x, const float* __restrict__ F,
                          const float* __restrict__ sv, const float* __restrict__ T,
                          const float* __restrict__ Q,
                          uint32_t kn0, uint32_t kn1)
{
    cudaTriggerProgrammaticLaunchCompletion();

    __shared__ float s_state[48];

    int tid = threadIdx.x;
    int warp = tid >> 5, lane = tid & 31;

    // ---- fused state transition + process noise (threads 0..15) ----
    if (tid < 16) {
        int p = blockIdx.x * 16 + tid;

        float l00 = sqrtf(Q[0]);
        float l10 = Q[3] / l00, l20 = Q[6] / l00;
        float l11 = sqrtf(Q[4] - l10 * l10);
        float l21 = (Q[7] - l20 * l10) / l11;
        float l22 = sqrtf(Q[8] - l20 * l20 - l21 * l21);

        float z[3];
#pragma unroll
        for (int d = 0; d < 3; ++d) {
            uint32_t b = tf32(kn0, kn1, (uint32_t)(3 * p + d));
            float f = __uint_as_float(0x3f800000u | (b >> 9)) - 1.0f;
            float val = __fadd_rn(__fmul_rn(f, 2.0f), -0.99999994f);
            val = fmaxf(-0.99999994f, val);
            z[d] = 1.41421356237f * erfinvf(val);
        }

        float s0 = sv[3 * p], s1 = sv[3 * p + 1], s2 = sv[3 * p + 2];
        float u0 = T[0] * s0 + T[1] * s1 + T[2] * s2;
        float u1 = T[3] * s0 + T[4] * s1 + T[5] * s2;
        float u2 = T[6] * s0 + T[7] * s1 + T[8] * s2;

        float o0 = u0 + z[0] * l00 + z[1] * l10 + z[2] * l20;
        float o1 = u1 + z[1] * l11 + z[2] * l21;
        float o2 = u2 + z[2] * l22;

        g_state[3 * p + 0] = o0;  s_state[3 * tid + 0] = o0;
        g_state[3 * p + 1] = o1;  s_state[3 * tid + 1] = o1;
        g_state[3 * p + 2] = o2;  s_state[3 * tid + 2] = o2;
    }
    __syncthreads();

    // ---- weights loop (EXACT round-9 form) ----
    int r0 = warp * 2;                    // row-in-block 0..15
    int a0 = blockIdx.x * 16 + r0;
    int a1 = a0 + 1;

    float s00 = s_state[3 * r0 + 0], s01 = s_state[3 * r0 + 1], s02 = s_state[3 * r0 + 2];
    float s10 = s_state[3 * r0 + 3], s11 = s_state[3 * r0 + 4], s12 = s_state[3 * r0 + 5];

    const float4* x0 = reinterpret_cast<const float4*>(x + (size_t)a0 * NP);
    const float4* x1 = reinterpret_cast<const float4*>(x + (size_t)a1 * NP);
    const float4* Fv = reinterpret_cast<const float4*>(F);

    float acc0 = 0.0f, acc1 = 0.0f;
#pragma unroll 4
    for (int it = 0; it < NP / 128; ++it) {
        int b4 = it * 32 + lane;
        float4 xa = __ldg(x0 + b4);
        float4 xb = __ldg(x1 + b4);
        float4 f0 = __ldg(Fv + 3 * b4 + 0);
        float4 f1 = __ldg(Fv + 3 * b4 + 1);
        float4 f2 = __ldg(Fv + 3 * b4 + 2);
        float p0 = f0.x * s00 + f0.y * s01 + f0.z * s02;
        float p1 = f0.w * s00 + f1.x * s01 + f1.y * s02;
        float p2 = f1.z * s00 + f1.w * s01 + f2.x * s02;
        float p3 = f2.y * s00 + f2.z * s01 + f2.w * s02;
        float q0 = f0.x * s10 + f0.y * s11 + f0.z * s12;
        float q1 = f0.w * s10 + f1.x * s11 + f1.y * s12;
        float q2 = f1.z * s10 + f1.w * s11 + f2.x * s12;
        float q3 = f2.y * s10 + f2.z * s11 + f2.w * s12;
        float d;
        d = xa.x - p0; acc0 = fmaf(d, d, acc0);
        d = xa.y - p1; acc0 = fmaf(d, d, acc0);
        d = xa.z - p2; acc0 = fmaf(d, d, acc0);
        d = xa.w - p3; acc0 = fmaf(d, d, acc0);
        d = xb.x - q0; acc1 = fmaf(d, d, acc1);
        d = xb.y - q1; acc1 = fmaf(d, d, acc1);
        d = xb.z - q2; acc1 = fmaf(d, d, acc1);
        d = xb.w - q3; acc1 = fmaf(d, d, acc1);
    }
#pragma unroll
    for (int o = 16; o; o >>= 1) {
        acc0 += __shfl_down_sync(0xffffffffu, acc0, o);
        acc1 += __shfl_down_sync(0xffffffffu, acc1, o);
    }
    if (lane == 0) {
        g_invw[a0] = 1.0f / acc0;
        g_invw[a1] = 1.0f / acc1;
    }
    __syncthreads();                 // all warps' state+invw stores issued
    if (tid == 0) {
        __threadfence();             // make g_state & g_invw visible device-wide
        atomicAdd(&g_wdone, 1);      // signal this block's completion
    }
}

// ---------------- kernel C: categorical + fused mean-of-gathered ----------
// B[32] MUST live in registers: the main loop is now FULLY UNROLLED (constant
// indices) and launch_bounds grants an ~85-reg budget (3 blocks/SM = 24
// warps, ample for an issue-bound kernel). Round 13 profile showed regs=32 +
// L1 16% = B spilled to local by the old `#pragma unroll 1`.
__global__ void __launch_bounds__(256, 3)
k_cat(uint32_t kc0, uint32_t kc1, float* __restrict__ out)
{
    const int row = blockIdx.x;
    const int t = threadIdx.x;
    const float INF = __int_as_float(0x7f800000);
    int lane = t & 31, warp = t >> 5;

    __shared__ float shv[8];
    __shared__ int   shi[8];
    __shared__ float sthr;

    const uint32_t base = (uint32_t)row * (uint32_t)NP;

    // ---- Phase A: PRNG only (independent of k_weights output) ----
    uint32_t B[32];
#pragma unroll
    for (int k = 0; k < 8; ++k) {
        uint32_t n0 = base + (uint32_t)((k << 10) + 4 * t);
        B[4 * k + 0] = tf32(kc0, kc1, n0 + 0u);
        B[4 * k + 1] = tf32(kc0, kc1, n0 + 1u);
        B[4 * k + 2] = tf32(kc0, kc1, n0 + 2u);
        B[4 * k + 3] = tf32(kc0, kc1, n0 + 3u);
    }

    // ---- Gate: wait for k_weights (g_state + g_invw) complete & visible ----
    cudaGridDependencySynchronize();          // PDL bookkeeping (cheap)
    if (t == 0) {
        while (atomicAdd(&g_wdone, 0) < NWB)
            __nanosleep(64);
    }
    __syncthreads();
    __threadfence();                          // acquire

    const float4* invw4 = reinterpret_cast<const float4*>(g_invw);

    // ---- prologue: k=0, j = 4t..4t+3, all exact; seeds the threshold ----
    float mv = INF;
    int   mi = 0;
    {
        int j0 = 4 * t;
        float4 iw = __ldg(invw4 + t);
        float v0 = exact_v(B[0], iw.x);
        float v1 = exact_v(B[1], iw.y);
        float v2 = exact_v(B[2], iw.z);
        float v3 = exact_v(B[3], iw.w);
        mv = v0; mi = j0;
        if (v1 < mv) { mv = v1; mi = j0 + 1; }
        if (v2 < mv) { mv = v2; mi = j0 + 2; }
        if (v3 < mv) { mv = v3; mi = j0 + 3; }

        float tv = mv;
#pragma unroll
        for (int o = 16; o; o >>= 1)
            tv = fminf(tv, __shfl_xor_sync(0xffffffffu, tv, o));
        if (lane == 0) shv[warp] = tv;
        __syncthreads();
        if (t == 0) {
            float m = shv[0];
#pragma unroll
            for (int wq = 1; wq < 8; ++wq) m = fminf(m, shv[wq]);
            sthr = m * 1.000004f;   // fudged static threshold
        }
        __syncthreads();
    }
    const float thr2 = sthr;
    __syncthreads();   // shv reused below; everyone read sthr

    // ---- main loop: k = 1..7, FULLY UNROLLED (B stays in registers) ----
#pragma unroll
    for (int k = 1; k < 8; ++k) {
        int j0 = (k << 10) + 4 * t;
        float4 iw = __ldg(invw4 + (k << 8) + t);
        uint32_t b0 = B[4 * k + 0];
        uint32_t b1 = B[4 * k + 1];
        uint32_t b2 = B[4 * k + 2];
        uint32_t b3 = B[4 * k + 3];

        uint32_t t0 = __umulhi(b0, 0x00800000u) + 0x3f800000u;
        uint32_t t1 = __umulhi(b1, 0x00800000u) + 0x3f800000u;
        uint32_t t2 = __umulhi(b2, 0x00800000u) + 0x3f800000u;
        uint32_t t3 = __umulhi(b3, 0x00800000u) + 0x3f800000u;
        float e0 = (2.0f - __uint_as_float(t0)) * iw.x;   // s = 1-u, exact
        float e1 = (2.0f - __uint_as_float(t1)) * iw.y;
        float e2 = (2.0f - __uint_as_float(t2)) * iw.z;
        float e3 = (2.0f - __uint_as_float(t3)) * iw.w;
        float emin = fminf(fminf(e0, e1), fminf(e2, e3));

        if (__ballot_sync(0xffffffffu, emin <= thr2)) {
            float v0 = exact_v(b0, iw.x);
            if (v0 < mv) { mv = v0; mi = j0; }
            float v1 = exact_v(b1, iw.y);
            if (v1 < mv) { mv = v1; mi = j0 + 1; }
            float v2 = exact_v(b2, iw.z);
            if (v2 < mv) { mv = v2; mi = j0 + 2; }
            float v3 = exact_v(b3, iw.w);
            if (v3 < mv) { mv = v3; mi = j0 + 3; }
        }
    }

    // ---- block argmin reduce (value, then lower index on exact ties) ----
#pragma unroll
    for (int o = 16; o; o >>= 1) {
        float ov = __shfl_down_sync(0xffffffffu, mv, o);
        int   oi = __shfl_down_sync(0xffffffffu, mi, o);
        if (ov < mv || (ov == mv && oi < mi)) { mv = ov; mi = oi; }
    }
    if (lane == 0) { shv[warp] = mv; shi[warp] = mi; }
    __syncthreads();
    if (warp == 0) {
        float v2 = (lane < 8) ? shv[lane] : INF;
        int   i2 = (lane < 8) ? shi[lane] : 0x7fffffff;
#pragma unroll
        for (int o = 4; o; o >>= 1) {
            float ov = __shfl_down_sync(0xffffffffu, v2, o);
            int   oi = __shfl_down_sync(0xffffffffu, i2, o);
            if (ov < v2 || (ov == v2 && oi < i2)) { v2 = ov; i2 = oi; }
        }
        if (lane == 0) {
            atomicAdd(&g_sum[0], g_state[3 * i2 + 0]);
            atomicAdd(&g_sum[1], g_state[3 * i2 + 1]);
            atomicAdd(&g_sum[2], g_state[3 * i2 + 2]);
            __threadfence();
            if (atomicAdd(&g_done, 1) == (int)gridDim.x - 1) {
                out[0] = g_sum[0] * (1.0f / NP);
                out[1] = g_sum[1] * (1.0f / NP);
                out[2] = g_sum[2] * (1.0f / NP);
                // reset for the next stream-ordered launch (graph replay)
                g_sum[0] = 0.0f; g_sum[1] = 0.0f; g_sum[2] = 0.0f;
                g_wdone = 0;
                __threadfence();
                g_done = 0;
            }
        }
    }
}

// ---------------- host: key derivation (fold-like split) ------------------
static void h_tf(uint32_t k0, uint32_t k1, uint32_t x0, uint32_t x1,
                 uint32_t& y0, uint32_t& y1)
{
    uint32_t k2 = k0 ^ k1 ^ 0x1BD11BDAu;
    x0 += k0; x1 += k1;
    const int R0[4] = {13, 15, 26, 6}, R1[4] = {17, 29, 16, 24};
    const int* RS[5] = {R0, R1, R0, R1, R0};
    const uint32_t ks[3] = {k0, k1, k2};
    for (int g = 0; g < 5; ++g) {
        for (int q = 0; q < 4; ++q) {
            x0 += x1;
            int r = RS[g][q];
            x1 = (x1 << r) | (x1 >> (32 - r));
            x1 ^= x0;
        }
        x0 += ks[(g + 1) % 3];
        x1 += ks[(g + 2) % 3] + (uint32_t)(g + 1);
    }
    y0 = x0; y1 = x1;
}

extern "C" void kernel_launch(void* const* d_in, const int* in_sizes, int n_in,
                              void* d_out, int out_size)
{
    const float* x  = (const float*)d_in[0];  // inputs (1, C, P)
    const float* sv = (const float*)d_in[1];  // state_vector (P, 3)
    const float* T  = (const float*)d_in[2];  // transition (3, 3)
    const float* Q  = (const float*)d_in[3];  // process noise cov (3, 3)
    const float* F  = (const float*)d_in[4];  // forward_matrix (C, 3)

    uint32_t kn0, kn1, kc0, kc1;
    h_tf(0u, 42u, 0u, 0u, kn0, kn1);  // k_noise
    h_tf(0u, 42u, 0u, 1u, kc0, kc1);  // k_cat

    k_weights<<<NWB, 256>>>(x, F, sv, T, Q, kn0, kn1);

    // k_cat with Programmatic Dependent Launch: Phase A (pure PRNG) overlaps
    // k_weights; the g_wdone flag (not the PDL sync) guards state/invw reads.
    cudaLaunchConfig_t cfg = {};
    cfg.gridDim = dim3(NP, 1, 1);
    cfg.blockDim = dim3(256, 1, 1);
    cudaLaunchAttribute attrs[1];
    attrs[0].id = cudaLaunchAttributeProgrammaticStreamSerialization;
    attrs[0].val.programmaticStreamSerializationAllowed = 1;
    cfg.attrs = attrs;
    cfg.numAttrs = 1;
    cudaError_t e = cudaLaunchKernelEx(&cfg, k_cat, kc0, kc1, (float*)d_out);
    if (e != cudaSuccess) {
        // Fallback: plain serialized launch (gate passes immediately).
        k_cat<<<NP, 256>>>(kc0, kc1, (float*)d_out);
    }
}

// round 15
// speedup vs baseline: 1.0437x; 1.0437x over previous
#include <cuda_runtime.h>
#include <cstdint>
#include <math.h>

#define NP 8192            // particles == channels
#define NWB (NP / 16)      // weights groups (512), handled by blocks 0..511

// ---------------- device scratch (no allocations allowed) ----------------
// Zero-initialized at module load; the LAST block of each launch resets the
// flags/accumulators for the next launch (stream-ordered).
__device__ float g_state[NP * 3];
__device__ float g_invw[NP];
__device__ float g_sum[3];
__device__ int   g_done;
__device__ int   g_wdone;   // weights completion counter (software flag)

// ---------------- threefry2x32 (JAX rotation schedule) -------------------
__device__ __forceinline__ uint32_t tf32(uint32_t k0, uint32_t k1, uint32_t n)
{
    uint32_t k2 = k0 ^ k1 ^ 0x1BD11BDAu;
    uint32_t x0 = k0;          // 0 + ks[0]
    uint32_t x1 = n + k1;      // n + ks[1]
#define TFR(r) { x0 += x1; x1 = __funnelshift_l(x1, x1, (r)); x1 ^= x0; }
    TFR(13) TFR(15) TFR(26) TFR(6)
    x0 += k1; x1 += k2 + 1u;
    TFR(17) TFR(29) TFR(16) TFR(24)
    x0 += k2; x1 += k0 + 2u;
    TFR(13) TFR(15) TFR(26) TFR(6)
    x0 += k0; x1 += k1 + 3u;
    TFR(17) TFR(29) TFR(16) TFR(24)
    x0 += k1; x1 += k2 + 4u;
    TFR(13) TFR(15) TFR(26) TFR(6)
    x0 += k2; x1 += k0 + 5u;
#undef TFR
    return x0 ^ x1;
}

// exact v for the categorical: v = (-logf(u)) * invw, identical arithmetic
// to the validated round-1 kernel (bitwise-stable selection).
__device__ __forceinline__ float exact_v(uint32_t b, float invw)
{
    uint32_t tbits = __umulhi(b, 0x00800000u) + 0x3f800000u; // 1 + (b>>9)*2^-23
    float f = __uint_as_float(tbits) - 1.0f;
    float u = fmaxf(f, 1.17549435e-38f);
    float e = -logf(u);
    return e * invw;
}

// ---------------- ONE fused kernel ----------------------------------------
// Blocks 0..NWB-1: weights phase for row-group (16 rows) first (incl. fused
//                  state transition), signal g_wdone, then their cat row.
// Blocks >= NWB:   cat Phase A immediately (overlaps the weights stream on
//                  wave-1 SM slots), then gate-spin, then Phase B.
// Cat structure is EXACTLY the round-13 measured-best form (B[32] in local
// via `#pragma unroll 1` Phase-B loop; 57-warp occupancy hides it).
__global__ void k_fused(const float* __restrict__ x, const float* __restrict__ F,
                        const float* __restrict__ sv, const float* __restrict__ T,
                        const float* __restrict__ Q,
                        uint32_t kn0, uint32_t kn1,
                        uint32_t kc0, uint32_t kc1,
                        float* __restrict__ out)
{
    const int row = blockIdx.x;
    const int t = threadIdx.x;
    const float INF = __int_as_float(0x7f800000);
    int lane = t & 31, warp = t >> 5;

    __shared__ float s_state[48];
    __shared__ float shv[8];
    __shared__ int   shi[8];
    __shared__ float sthr;

    // =================== weights phase (blocks 0..NWB-1) ===================
    if (row < NWB) {
        // ---- fused state transition + process noise (threads 0..15) ----
        if (t < 16) {
            int p = row * 16 + t;

            float l00 = sqrtf(Q[0]);
            float l10 = Q[3] / l00, l20 = Q[6] / l00;
            float l11 = sqrtf(Q[4] - l10 * l10);
            float l21 = (Q[7] - l20 * l10) / l11;
            float l22 = sqrtf(Q[8] - l20 * l20 - l21 * l21);

            float z[3];
#pragma unroll
            for (int d = 0; d < 3; ++d) {
                uint32_t b = tf32(kn0, kn1, (uint32_t)(3 * p + d));
                float f = __uint_as_float(0x3f800000u | (b >> 9)) - 1.0f;
                float val = __fadd_rn(__fmul_rn(f, 2.0f), -0.99999994f);
                val = fmaxf(-0.99999994f, val);
                z[d] = 1.41421356237f * erfinvf(val);
            }

            float s0 = sv[3 * p], s1 = sv[3 * p + 1], s2 = sv[3 * p + 2];
            float u0 = T[0] * s0 + T[1] * s1 + T[2] * s2;
            float u1 = T[3] * s0 + T[4] * s1 + T[5] * s2;
            float u2 = T[6] * s0 + T[7] * s1 + T[8] * s2;

            float o0 = u0 + z[0] * l00 + z[1] * l10 + z[2] * l20;
            float o1 = u1 + z[1] * l11 + z[2] * l21;
            float o2 = u2 + z[2] * l22;

            g_state[3 * p + 0] = o0;  s_state[3 * t + 0] = o0;
            g_state[3 * p + 1] = o1;  s_state[3 * t + 1] = o1;
            g_state[3 * p + 2] = o2;  s_state[3 * t + 2] = o2;
        }
        __syncthreads();

        // ---- weights loop (round-9 validated arithmetic; unroll 2 to cap
        //      register pressure so the cat phase keeps ~6 blocks/SM) ----
        int r0 = warp * 2;
        int a0 = row * 16 + r0;
        int a1 = a0 + 1;

        float s00 = s_state[3 * r0 + 0], s01 = s_state[3 * r0 + 1], s02 = s_state[3 * r0 + 2];
        float s10 = s_state[3 * r0 + 3], s11 = s_state[3 * r0 + 4], s12 = s_state[3 * r0 + 5];

        const float4* x0 = reinterpret_cast<const float4*>(x + (size_t)a0 * NP);
        const float4* x1 = reinterpret_cast<const float4*>(x + (size_t)a1 * NP);
        const float4* Fv = reinterpret_cast<const float4*>(F);

        float acc0 = 0.0f, acc1 = 0.0f;
#pragma unroll 2
        for (int it = 0; it < NP / 128; ++it) {
            int b4 = it * 32 + lane;
            float4 xa = __ldg(x0 + b4);
            float4 xb = __ldg(x1 + b4);
            float4 f0 = __ldg(Fv + 3 * b4 + 0);
            float4 f1 = __ldg(Fv + 3 * b4 + 1);
            float4 f2 = __ldg(Fv + 3 * b4 + 2);
            float p0 = f0.x * s00 + f0.y * s01 + f0.z * s02;
            float p1 = f0.w * s00 + f1.x * s01 + f1.y * s02;
            float p2 = f1.z * s00 + f1.w * s01 + f2.x * s02;
            float p3 = f2.y * s00 + f2.z * s01 + f2.w * s02;
            float q0 = f0.x * s10 + f0.y * s11 + f0.z * s12;
            float q1 = f0.w * s10 + f1.x * s11 + f1.y * s12;
            float q2 = f1.z * s10 + f1.w * s11 + f2.x * s12;
            float q3 = f2.y * s10 + f2.z * s11 + f2.w * s12;
            float d;
            d = xa.x - p0; acc0 = fmaf(d, d, acc0);
            d = xa.y - p1; acc0 = fmaf(d, d, acc0);
            d = xa.z - p2; acc0 = fmaf(d, d, acc0);
            d = xa.w - p3; acc0 = fmaf(d, d, acc0);
            d = xb.x - q0; acc1 = fmaf(d, d, acc1);
            d = xb.y - q1; acc1 = fmaf(d, d, acc1);
            d = xb.z - q2; acc1 = fmaf(d, d, acc1);
            d = xb.w - q3; acc1 = fmaf(d, d, acc1);
        }
#pragma unroll
        for (int o = 16; o; o >>= 1) {
            acc0 += __shfl_down_sync(0xffffffffu, acc0, o);
            acc1 += __shfl_down_sync(0xffffffffu, acc1, o);
        }
        if (lane == 0) {
            g_invw[a0] = 1.0f / acc0;
            g_invw[a1] = 1.0f / acc1;
        }
        __syncthreads();                 // all warps' state+invw stores issued
        if (t == 0) {
            __threadfence();             // make g_state & g_invw visible
            atomicAdd(&g_wdone, 1);      // signal this group's completion
        }
        __syncthreads();
    }

    // =================== cat phase (ALL blocks; round-13 form) =============
    const uint32_t base = (uint32_t)row * (uint32_t)NP;

    // ---- Phase A: PRNG only (no dependence on weights output) ----
    uint32_t B[32];
#pragma unroll
    for (int k = 0; k < 8; ++k) {
        uint32_t n0 = base + (uint32_t)((k << 10) + 4 * t);
        B[4 * k + 0] = tf32(kc0, kc1, n0 + 0u);
        B[4 * k + 1] = tf32(kc0, kc1, n0 + 1u);
        B[4 * k + 2] = tf32(kc0, kc1, n0 + 2u);
        B[4 * k + 3] = tf32(kc0, kc1, n0 + 3u);
    }

    // ---- Gate: wait for all weights groups complete & visible ----
    if (t == 0) {
        while (atomicAdd(&g_wdone, 0) < NWB)
            __nanosleep(64);
    }
    __syncthreads();
    __threadfence();                          // acquire

    const float4* invw4 = reinterpret_cast<const float4*>(g_invw);

    // ---- prologue: k=0, j = 4t..4t+3, all exact; seeds the threshold ----
    float mv = INF;
    int   mi = 0;
    {
        int j0 = 4 * t;
        float4 iw = __ldg(invw4 + t);
        float v0 = exact_v(B[0], iw.x);
        float v1 = exact_v(B[1], iw.y);
        float v2 = exact_v(B[2], iw.z);
        float v3 = exact_v(B[3], iw.w);
        mv = v0; mi = j0;
        if (v1 < mv) { mv = v1; mi = j0 + 1; }
        if (v2 < mv) { mv = v2; mi = j0 + 2; }
        if (v3 < mv) { mv = v3; mi = j0 + 3; }

        float tv = mv;
#pragma unroll
        for (int o = 16; o; o >>= 1)
            tv = fminf(tv, __shfl_xor_sync(0xffffffffu, tv, o));
        if (lane == 0) shv[warp] = tv;
        __syncthreads();
        if (t == 0) {
            float m = shv[0];
#pragma unroll
            for (int wq = 1; wq < 8; ++wq) m = fminf(m, shv[wq]);
            sthr = m * 1.000004f;   // fudged static threshold
        }
        __syncthreads();
    }
    const float thr2 = sthr;
    __syncthreads();   // shv reused below; everyone read sthr

    // ---- main loop: k = 1..7, 4 elems/thread/iter, 1 ballot per group ----
    // `#pragma unroll 1` keeps B in (coalesced, latency-hidden) local memory;
    // round 14 proved the register version costs more via occupancy loss.
#pragma unroll 1
    for (int k = 1; k < 8; ++k) {
        int j0 = (k << 10) + 4 * t;
        float4 iw = __ldg(invw4 + (k << 8) + t);
        uint32_t b0 = B[4 * k + 0];
        uint32_t b1 = B[4 * k + 1];
        uint32_t b2 = B[4 * k + 2];
        uint32_t b3 = B[4 * k + 3];

        uint32_t t0 = __umulhi(b0, 0x00800000u) + 0x3f800000u;
        uint32_t t1 = __umulhi(b1, 0x00800000u) + 0x3f800000u;
        uint32_t t2 = __umulhi(b2, 0x00800000u) + 0x3f800000u;
        uint32_t t3 = __umulhi(b3, 0x00800000u) + 0x3f800000u;
        float e0 = (2.0f - __uint_as_float(t0)) * iw.x;   // s = 1-u, exact
        float e1 = (2.0f - __uint_as_float(t1)) * iw.y;
        float e2 = (2.0f - __uint_as_float(t2)) * iw.z;
        float e3 = (2.0f - __uint_as_float(t3)) * iw.w;
        float emin = fminf(fminf(e0, e1), fminf(e2, e3));

        if (__ballot_sync(0xffffffffu, emin <= thr2)) {
            float v0 = exact_v(b0, iw.x);
            if (v0 < mv) { mv = v0; mi = j0; }
            float v1 = exact_v(b1, iw.y);
            if (v1 < mv) { mv = v1; mi = j0 + 1; }
            float v2 = exact_v(b2, iw.z);
            if (v2 < mv) { mv = v2; mi = j0 + 2; }
            float v3 = exact_v(b3, iw.w);
            if (v3 < mv) { mv = v3; mi = j0 + 3; }
        }
    }

    // ---- block argmin reduce (value, then lower index on exact ties) ----
#pragma unroll
    for (int o = 16; o; o >>= 1) {
        float ov = __shfl_down_sync(0xffffffffu, mv, o);
        int   oi = __shfl_down_sync(0xffffffffu, mi, o);
        if (ov < mv || (ov == mv && oi < mi)) { mv = ov; mi = oi; }
    }
    if (lane == 0) { shv[warp] = mv; shi[warp] = mi; }
    __syncthreads();
    if (warp == 0) {
        float v2 = (lane < 8) ? shv[lane] : INF;
        int   i2 = (lane < 8) ? shi[lane] : 0x7fffffff;
#pragma unroll
        for (int o = 4; o; o >>= 1) {
            float ov = __shfl_down_sync(0xffffffffu, v2, o);
            int   oi = __shfl_down_sync(0xffffffffu, i2, o);
            if (ov < v2 || (ov == v2 && oi < i2)) { v2 = ov; i2 = oi; }
        }
        if (lane == 0) {
            atomicAdd(&g_sum[0], g_state[3 * i2 + 0]);
            atomicAdd(&g_sum[1], g_state[3 * i2 + 1]);
            atomicAdd(&g_sum[2], g_state[3 * i2 + 2]);
            __threadfence();
            if (atomicAdd(&g_done, 1) == (int)gridDim.x - 1) {
                out[0] = g_sum[0] * (1.0f / NP);
                out[1] = g_sum[1] * (1.0f / NP);
                out[2] = g_sum[2] * (1.0f / NP);
                // reset for the next stream-ordered launch (graph replay)
                g_sum[0] = 0.0f; g_sum[1] = 0.0f; g_sum[2] = 0.0f;
                g_wdone = 0;
                __threadfence();
                g_done = 0;
            }
        }
    }
}

// ---------------- host: key derivation (fold-like split) ------------------
static void h_tf(uint32_t k0, uint32_t k1, uint32_t x0, uint32_t x1,
                 uint32_t& y0, uint32_t& y1)
{
    uint32_t k2 = k0 ^ k1 ^ 0x1BD11BDAu;
    x0 += k0; x1 += k1;
    const int R0[4] = {13, 15, 26, 6}, R1[4] = {17, 29, 16, 24};
    const int* RS[5] = {R0, R1, R0, R1, R0};
    const uint32_t ks[3] = {k0, k1, k2};
    for (int g = 0; g < 5; ++g) {
        for (int q = 0; q < 4; ++q) {
            x0 += x1;
            int r = RS[g][q];
            x1 = (x1 << r) | (x1 >> (32 - r));
            x1 ^= x0;
        }
        x0 += ks[(g + 1) % 3];
        x1 += ks[(g + 2) % 3] + (uint32_t)(g + 1);
    }
    y0 = x0; y1 = x1;
}

extern "C" void kernel_launch(void* const* d_in, const int* in_sizes, int n_in,
                              void* d_out, int out_size)
{
    const float* x  = (const float*)d_in[0];  // inputs (1, C, P)
    const float* sv = (const float*)d_in[1];  // state_vector (P, 3)
    const float* T  = (const float*)d_in[2];  // transition (3, 3)
    const float* Q  = (const float*)d_in[3];  // process noise cov (3, 3)
    const float* F  = (const float*)d_in[4];  // forward_matrix (C, 3)

    uint32_t kn0, kn1, kc0, kc1;
    h_tf(0u, 42u, 0u, 0u, kn0, kn1);  // k_noise
    h_tf(0u, 42u, 0u, 1u, kc0, kc1);  // k_cat

    // ONE kernel: weights (blocks 0..511, guaranteed wave-1 resident) overlap
    // cat Phase A intrinsically — no PDL, no graph-replay serialization risk.
    k_fused<<<NP, 256>>>(x, F, sv, T, Q, kn0, kn1, kc0, kc1, (float*)d_out);
}

// round 16
// speedup vs baseline: 1.1475x; 1.0994x over previous
#include <cuda_runtime.h>
#include <cstdint>
#include <math.h>

#define NP 8192            // particles == channels
#define NWB (NP / 16)      // k_weights grid size (512 blocks)

// ---------------- device scratch (no allocations allowed) ----------------
__device__ float g_state[NP * 3];
__device__ float g_invw[NP];
__device__ float g_sum[3];
__device__ int   g_done;
__device__ int   g_wdone;   // k_weights completion counter (software flag)

// ---------------- threefry2x32 (JAX rotation schedule) -------------------
__device__ __forceinline__ uint32_t tf32(uint32_t k0, uint32_t k1, uint32_t n)
{
    uint32_t k2 = k0 ^ k1 ^ 0x1BD11BDAu;
    uint32_t x0 = k0;          // 0 + ks[0]
    uint32_t x1 = n + k1;      // n + ks[1]
#define TFR(r) { x0 += x1; x1 = __funnelshift_l(x1, x1, (r)); x1 ^= x0; }
    TFR(13) TFR(15) TFR(26) TFR(6)
    x0 += k1; x1 += k2 + 1u;
    TFR(17) TFR(29) TFR(16) TFR(24)
    x0 += k2; x1 += k0 + 2u;
    TFR(13) TFR(15) TFR(26) TFR(6)
    x0 += k0; x1 += k1 + 3u;
    TFR(17) TFR(29) TFR(16) TFR(24)
    x0 += k1; x1 += k2 + 4u;
    TFR(13) TFR(15) TFR(26) TFR(6)
    x0 += k2; x1 += k0 + 5u;
#undef TFR
    return x0 ^ x1;
}

// exact v for the categorical: v = (-logf(u)) * invw, identical arithmetic
// to the validated round-1 kernel (bitwise-stable selection).
__device__ __forceinline__ float exact_v(uint32_t b, float invw)
{
    uint32_t tbits = __umulhi(b, 0x00800000u) + 0x3f800000u; // 1 + (b>>9)*2^-23
    float f = __uint_as_float(tbits) - 1.0f;
    float u = fmaxf(f, 1.17549435e-38f);
    float e = -logf(u);
    return e * invw;
}

// ---------------- kernel A: state transition + process noise -------------
__global__ void k_state(const float* __restrict__ sv,
                        const float* __restrict__ T,
                        const float* __restrict__ Q,
                        uint32_t kn0, uint32_t kn1)
{
    int p = blockIdx.x * 128 + threadIdx.x;
    if (p < 3) g_sum[p] = 0.0f;   // reset accumulators each launch (graph replay)
    if (p == 3) g_done = 0;
    if (p == 4) g_wdone = 0;
    if (p >= NP) return;

    float l00 = sqrtf(Q[0]);
    float l10 = Q[3] / l00, l20 = Q[6] / l00;
    float l11 = sqrtf(Q[4] - l10 * l10);
    float l21 = (Q[7] - l20 * l10) / l11;
    float l22 = sqrtf(Q[8] - l20 * l20 - l21 * l21);

    float z[3];
#pragma unroll
    for (int d = 0; d < 3; ++d) {
        uint32_t b = tf32(kn0, kn1, (uint32_t)(3 * p + d));
        float f = __uint_as_float(0x3f800000u | (b >> 9)) - 1.0f;
        float val = __fadd_rn(__fmul_rn(f, 2.0f), -0.99999994f);
        val = fmaxf(-0.99999994f, val);
        z[d] = 1.41421356237f * erfinvf(val);
    }

    float s0 = sv[3 * p], s1 = sv[3 * p + 1], s2 = sv[3 * p + 2];
    float u0 = T[0] * s0 + T[1] * s1 + T[2] * s2;
    float u1 = T[3] * s0 + T[4] * s1 + T[5] * s2;
    float u2 = T[6] * s0 + T[7] * s1 + T[8] * s2;

    g_state[3 * p + 0] = u0 + z[0] * l00 + z[1] * l10 + z[2] * l20;
    g_state[3 * p + 1] = u1 + z[1] * l11 + z[2] * l21;
    g_state[3 * p + 2] = u2 + z[2] * l22;
}

// ---------------- kernel B: w[a] = sum_b (x[a,b] - F[b].s_a)^2 ------------
// Round-9 structure (measured best) with two MLP tweaks: unroll 8 (wider
// load window for the DRAM stream) and __ldcs on the read-once x rows
// (streaming evict -> keeps F resident in L2).
__global__ void k_weights(const float* __restrict__ x, const float* __restrict__ F)
{
    cudaTriggerProgrammaticLaunchCompletion();

    int warp = threadIdx.x >> 5, lane = threadIdx.x & 31;
    int a0 = blockIdx.x * 16 + warp * 2;
    int a1 = a0 + 1;

    float s00 = g_state[3 * a0], s01 = g_state[3 * a0 + 1], s02 = g_state[3 * a0 + 2];
    float s10 = g_state[3 * a1], s11 = g_state[3 * a1 + 1], s12 = g_state[3 * a1 + 2];

    const float4* x0 = reinterpret_cast<const float4*>(x + (size_t)a0 * NP);
    const float4* x1 = reinterpret_cast<const float4*>(x + (size_t)a1 * NP);
    const float4* Fv = reinterpret_cast<const float4*>(F);

    float acc0 = 0.0f, acc1 = 0.0f;
#pragma unroll 8
    for (int it = 0; it < NP / 128; ++it) {
        int b4 = it * 32 + lane;
        float4 xa = __ldcs(x0 + b4);
        float4 xb = __ldcs(x1 + b4);
        float4 f0 = __ldg(Fv + 3 * b4 + 0);
        float4 f1 = __ldg(Fv + 3 * b4 + 1);
        float4 f2 = __ldg(Fv + 3 * b4 + 2);
        float p0 = f0.x * s00 + f0.y * s01 + f0.z * s02;
        float p1 = f0.w * s00 + f1.x * s01 + f1.y * s02;
        float p2 = f1.z * s00 + f1.w * s01 + f2.x * s02;
        float p3 = f2.y * s00 + f2.z * s01 + f2.w * s02;
        float q0 = f0.x * s10 + f0.y * s11 + f0.z * s12;
        float q1 = f0.w * s10 + f1.x * s11 + f1.y * s12;
        float q2 = f1.z * s10 + f1.w * s11 + f2.x * s12;
        float q3 = f2.y * s10 + f2.z * s11 + f2.w * s12;
        float d;
        d = xa.x - p0; acc0 = fmaf(d, d, acc0);
        d = xa.y - p1; acc0 = fmaf(d, d, acc0);
        d = xa.z - p2; acc0 = fmaf(d, d, acc0);
        d = xa.w - p3; acc0 = fmaf(d, d, acc0);
        d = xb.x - q0; acc1 = fmaf(d, d, acc1);
        d = xb.y - q1; acc1 = fmaf(d, d, acc1);
        d = xb.z - q2; acc1 = fmaf(d, d, acc1);
        d = xb.w - q3; acc1 = fmaf(d, d, acc1);
    }
#pragma unroll
    for (int o = 16; o; o >>= 1) {
        acc0 += __shfl_down_sync(0xffffffffu, acc0, o);
        acc1 += __shfl_down_sync(0xffffffffu, acc1, o);
    }
    if (lane == 0) {
        g_invw[a0] = 1.0f / acc0;
        g_invw[a1] = 1.0f / acc1;
    }
    __syncthreads();                 // all warps' stores issued
    if (threadIdx.x == 0) {
        __threadfence();             // make g_invw visible device-wide
        atomicAdd(&g_wdone, 1);      // signal this block's completion
    }
}

// ---------------- kernel C: categorical + fused mean-of-gathered ----------
// EXACT round-12/13 measured-best form (k_cat @190.4us, alu 90.5%):
// Phase A into B[32] (local via `#pragma unroll 1`, latency-hidden at 89%
// occupancy — round 14 proved the register version is worse), static
// threshold from k=0, one ballot per 4-elem group via fminf-tree.
__global__ void k_cat(uint32_t kc0, uint32_t kc1, float* __restrict__ out)
{
    const int row = blockIdx.x;
    const int t = threadIdx.x;
    const float INF = __int_as_float(0x7f800000);
    int lane = t & 31, warp = t >> 5;

    __shared__ float shv[8];
    __shared__ int   shi[8];
    __shared__ float sthr;

    const uint32_t base = (uint32_t)row * (uint32_t)NP;

    // ---- Phase A: PRNG only (independent of k_weights output) ----
    uint32_t B[32];
#pragma unroll
    for (int k = 0; k < 8; ++k) {
        uint32_t n0 = base + (uint32_t)((k << 10) + 4 * t);
        B[4 * k + 0] = tf32(kc0, kc1, n0 + 0u);
        B[4 * k + 1] = tf32(kc0, kc1, n0 + 1u);
        B[4 * k + 2] = tf32(kc0, kc1, n0 + 2u);
        B[4 * k + 3] = tf32(kc0, kc1, n0 + 3u);
    }

    // ---- Gate: wait for k_weights' g_invw to be complete & visible ----
    cudaGridDependencySynchronize();          // PDL bookkeeping (cheap)
    if (t == 0) {
        while (atomicAdd(&g_wdone, 0) < NWB)
            __nanosleep(64);
    }
    __syncthreads();
    __threadfence();                          // acquire

    const float4* invw4 = reinterpret_cast<const float4*>(g_invw);

    // ---- prologue: k=0, j = 4t..4t+3, all exact; seeds the threshold ----
    float mv = INF;
    int   mi = 0;
    {
        int j0 = 4 * t;
        float4 iw = __ldg(invw4 + t);
        float v0 = exact_v(B[0], iw.x);
        float v1 = exact_v(B[1], iw.y);
        float v2 = exact_v(B[2], iw.z);
        float v3 = exact_v(B[3], iw.w);
        mv = v0; mi = j0;
        if (v1 < mv) { mv = v1; mi = j0 + 1; }
        if (v2 < mv) { mv = v2; mi = j0 + 2; }
        if (v3 < mv) { mv = v3; mi = j0 + 3; }

        float tv = mv;
#pragma unroll
        for (int o = 16; o; o >>= 1)
            tv = fminf(tv, __shfl_xor_sync(0xffffffffu, tv, o));
        if (lane == 0) shv[warp] = tv;
        __syncthreads();
        if (t == 0) {
            float m = shv[0];
#pragma unroll
            for (int wq = 1; wq < 8; ++wq) m = fminf(m, shv[wq]);
            sthr = m * 1.000004f;   // fudged static threshold
        }
        __syncthreads();
    }
    const float thr2 = sthr;
    __syncthreads();   // shv reused below; everyone read sthr

    // ---- main loop: k = 1..7, 4 elems/thread/iter, 1 ballot per group ----
#pragma unroll 1
    for (int k = 1; k < 8; ++k) {
        int j0 = (k << 10) + 4 * t;
        float4 iw = __ldg(invw4 + (k << 8) + t);
        uint32_t b0 = B[4 * k + 0];
        uint32_t b1 = B[4 * k + 1];
        uint32_t b2 = B[4 * k + 2];
        uint32_t b3 = B[4 * k + 3];

        uint32_t t0 = __umulhi(b0, 0x00800000u) + 0x3f800000u;
        uint32_t t1 = __umulhi(b1, 0x00800000u) + 0x3f800000u;
        uint32_t t2 = __umulhi(b2, 0x00800000u) + 0x3f800000u;
        uint32_t t3 = __umulhi(b3, 0x00800000u) + 0x3f800000u;
        float e0 = (2.0f - __uint_as_float(t0)) * iw.x;   // s = 1-u, exact
        float e1 = (2.0f - __uint_as_float(t1)) * iw.y;
        float e2 = (2.0f - __uint_as_float(t2)) * iw.z;
        float e3 = (2.0f - __uint_as_float(t3)) * iw.w;
        float emin = fminf(fminf(e0, e1), fminf(e2, e3));

        if (__ballot_sync(0xffffffffu, emin <= thr2)) {
            float v0 = exact_v(b0, iw.x);
            if (v0 < mv) { mv = v0; mi = j0; }
            float v1 = exact_v(b1, iw.y);
            if (v1 < mv) { mv = v1; mi = j0 + 1; }
            float v2 = exact_v(b2, iw.z);
            if (v2 < mv) { mv = v2; mi = j0 + 2; }
            float v3 = exact_v(b3, iw.w);
            if (v3 < mv) { mv = v3; mi = j0 + 3; }
        }
    }

    // ---- block argmin reduce (value, then lower index on exact ties) ----
#pragma unroll
    for (int o = 16; o; o >>= 1) {
        float ov = __shfl_down_sync(0xffffffffu, mv, o);
        int   oi = __shfl_down_sync(0xffffffffu, mi, o);
        if (ov < mv || (ov == mv && oi < mi)) { mv = ov; mi = oi; }
    }
    if (lane == 0) { shv[warp] = mv; shi[warp] = mi; }
    __syncthreads();
    if (warp == 0) {
        float v2 = (lane < 8) ? shv[lane] : INF;
        int   i2 = (lane < 8) ? shi[lane] : 0x7fffffff;
#pragma unroll
        for (int o = 4; o; o >>= 1) {
            float ov = __shfl_down_sync(0xffffffffu, v2, o);
            int   oi = __shfl_down_sync(0xffffffffu, i2, o);
            if (ov < v2 || (ov == v2 && oi < i2)) { v2 = ov; i2 = oi; }
        }
        if (lane == 0) {
            atomicAdd(&g_sum[0], g_state[3 * i2 + 0]);
            atomicAdd(&g_sum[1], g_state[3 * i2 + 1]);
            atomicAdd(&g_sum[2], g_state[3 * i2 + 2]);
            __threadfence();
            if (atomicAdd(&g_done, 1) == (int)gridDim.x - 1) {
                out[0] = g_sum[0] * (1.0f / NP);
                out[1] = g_sum[1] * (1.0f / NP);
                out[2] = g_sum[2] * (1.0f / NP);
            }
        }
    }
}

// ---------------- host: key derivation (fold-like split) ------------------
static void h_tf(uint32_t k0, uint32_t k1, uint32_t x0, uint32_t x1,
                 uint32_t& y0, uint32_t& y1)
{
    uint32_t k2 = k0 ^ k1 ^ 0x1BD11BDAu;
    x0 += k0; x1 += k1;
    const int R0[4] = {13, 15, 26, 6}, R1[4] = {17, 29, 16, 24};
    const int* RS[5] = {R0, R1, R0, R1, R0};
    const uint32_t ks[3] = {k0, k1, k2};
    for (int g = 0; g < 5; ++g) {
        for (int q = 0; q < 4; ++q) {
            x0 += x1;
            int r = RS[g][q];
            x1 = (x1 << r) | (x1 >> (32 - r));
            x1 ^= x0;
        }
        x0 += ks[(g + 1) % 3];
        x1 += ks[(g + 2) % 3] + (uint32_t)(g + 1);
    }
    y0 = x0; y1 = x1;
}

extern "C" void kernel_launch(void* const* d_in, const int* in_sizes, int n_in,
                              void* d_out, int out_size)
{
    const float* x  = (const float*)d_in[0];  // inputs (1, C, P)
    const float* sv = (const float*)d_in[1];  // state_vector (P, 3)
    const float* T  = (const float*)d_in[2];  // transition (3, 3)
    const float* Q  = (const float*)d_in[3];  // process noise cov (3, 3)
    const float* F  = (const float*)d_in[4];  // forward_matrix (C, 3)

    uint32_t kn0, kn1, kc0, kc1;
    h_tf(0u, 42u, 0u, 0u, kn0, kn1);  // k_noise
    h_tf(0u, 42u, 0u, 1u, kc0, kc1);  // k_cat

    k_state  <<<NP / 128, 128>>>(sv, T, Q, kn0, kn1);
    k_weights<<<NWB, 256>>>(x, F);

    // k_cat with Programmatic Dependent Launch: Phase A (pure PRNG) overlaps
    // k_weights; the g_wdone flag (not the PDL sync) guards the invw reads.
    cudaLaunchConfig_t cfg = {};
    cfg.gridDim = dim3(NP, 1, 1);
    cfg.blockDim = dim3(256, 1, 1);
    cudaLaunchAttribute attrs[1];
    attrs[0].id = cudaLaunchAttributeProgrammaticStreamSerialization;
    attrs[0].val.programmaticStreamSerializationAllowed = 1;
    cfg.attrs = attrs;
    cfg.numAttrs = 1;
    cudaError_t e = cudaLaunchKernelEx(&cfg, k_cat, kc0, kc1, (float*)d_out);
    if (e != cudaSuccess) {
        // Fallback: plain serialized launch (gate passes immediately).
        k_cat<<<NP, 256>>>(kc0, kc1, (float*)d_out);
    }
}

// round 17
// speedup vs baseline: 1.1624x; 1.0130x over previous
#include <cuda_runtime.h>
#include <cstdint>
#include <math.h>

#define NP 8192            // particles == channels
#define NWB (NP / 16)      // k_weights grid size (512 blocks)

// ---------------- device scratch (no allocations allowed) ----------------
__device__ float g_state[NP * 3];
__device__ float g_invw[NP];
__device__ float g_sum[3];
__device__ int   g_done;
__device__ int   g_wdone;   // k_weights completion counter (software flag)

// ---------------- threefry2x32 (JAX rotation schedule) -------------------
__device__ __forceinline__ uint32_t tf32(uint32_t k0, uint32_t k1, uint32_t n)
{
    uint32_t k2 = k0 ^ k1 ^ 0x1BD11BDAu;
    uint32_t x0 = k0;          // 0 + ks[0]
    uint32_t x1 = n + k1;      // n + ks[1]
#define TFR(r) { x0 += x1; x1 = __funnelshift_l(x1, x1, (r)); x1 ^= x0; }
    TFR(13) TFR(15) TFR(26) TFR(6)
    x0 += k1; x1 += k2 + 1u;
    TFR(17) TFR(29) TFR(16) TFR(24)
    x0 += k2; x1 += k0 + 2u;
    TFR(13) TFR(15) TFR(26) TFR(6)
    x0 += k0; x1 += k1 + 3u;
    TFR(17) TFR(29) TFR(16) TFR(24)
    x0 += k1; x1 += k2 + 4u;
    TFR(13) TFR(15) TFR(26) TFR(6)
    x0 += k2; x1 += k0 + 5u;
#undef TFR
    return x0 ^ x1;
}

// exact v for the categorical: v = (-logf(u)) * invw, identical arithmetic
// to the validated round-1 kernel (bitwise-stable selection).
__device__ __forceinline__ float exact_v(uint32_t b, float invw)
{
    uint32_t tbits = __umulhi(b, 0x00800000u) + 0x3f800000u; // 1 + (b>>9)*2^-23
    float f = __uint_as_float(tbits) - 1.0f;
    float u = fmaxf(f, 1.17549435e-38f);
    float e = -logf(u);
    return e * invw;
}

// ---------------- kernel A: state transition + process noise -------------
__global__ void k_state(const float* __restrict__ sv,
                        const float* __restrict__ T,
                        const float* __restrict__ Q,
                        uint32_t kn0, uint32_t kn1)
{
    int p = blockIdx.x * 128 + threadIdx.x;
    if (p < 3) g_sum[p] = 0.0f;   // reset accumulators each launch (graph replay)
    if (p == 3) g_done = 0;
    if (p == 4) g_wdone = 0;
    if (p >= NP) return;

    float l00 = sqrtf(Q[0]);
    float l10 = Q[3] / l00, l20 = Q[6] / l00;
    float l11 = sqrtf(Q[4] - l10 * l10);
    float l21 = (Q[7] - l20 * l10) / l11;
    float l22 = sqrtf(Q[8] - l20 * l20 - l21 * l21);

    float z[3];
#pragma unroll
    for (int d = 0; d < 3; ++d) {
        uint32_t b = tf32(kn0, kn1, (uint32_t)(3 * p + d));
        float f = __uint_as_float(0x3f800000u | (b >> 9)) - 1.0f;
        float val = __fadd_rn(__fmul_rn(f, 2.0f), -0.99999994f);
        val = fmaxf(-0.99999994f, val);
        z[d] = 1.41421356237f * erfinvf(val);
    }

    float s0 = sv[3 * p], s1 = sv[3 * p + 1], s2 = sv[3 * p + 2];
    float u0 = T[0] * s0 + T[1] * s1 + T[2] * s2;
    float u1 = T[3] * s0 + T[4] * s1 + T[5] * s2;
    float u2 = T[6] * s0 + T[7] * s1 + T[8] * s2;

    g_state[3 * p + 0] = u0 + z[0] * l00 + z[1] * l10 + z[2] * l20;
    g_state[3 * p + 1] = u1 + z[1] * l11 + z[2] * l21;
    g_state[3 * p + 2] = u2 + z[2] * l22;
}

// ---------------- kernel B: w[a] = sum_b (x[a,b] - F[b].s_a)^2 ------------
// Round-16 measured-best form: unroll 8 + __ldcs streaming x loads.
__global__ void k_weights(const float* __restrict__ x, const float* __restrict__ F)
{
    cudaTriggerProgrammaticLaunchCompletion();

    int warp = threadIdx.x >> 5, lane = threadIdx.x & 31;
    int a0 = blockIdx.x * 16 + warp * 2;
    int a1 = a0 + 1;

    float s00 = g_state[3 * a0], s01 = g_state[3 * a0 + 1], s02 = g_state[3 * a0 + 2];
    float s10 = g_state[3 * a1], s11 = g_state[3 * a1 + 1], s12 = g_state[3 * a1 + 2];

    const float4* x0 = reinterpret_cast<const float4*>(x + (size_t)a0 * NP);
    const float4* x1 = reinterpret_cast<const float4*>(x + (size_t)a1 * NP);
    const float4* Fv = reinterpret_cast<const float4*>(F);

    float acc0 = 0.0f, acc1 = 0.0f;
#pragma unroll 8
    for (int it = 0; it < NP / 128; ++it) {
        int b4 = it * 32 + lane;
        float4 xa = __ldcs(x0 + b4);
        float4 xb = __ldcs(x1 + b4);
        float4 f0 = __ldg(Fv + 3 * b4 + 0);
        float4 f1 = __ldg(Fv + 3 * b4 + 1);
        float4 f2 = __ldg(Fv + 3 * b4 + 2);
        float p0 = f0.x * s00 + f0.y * s01 + f0.z * s02;
        float p1 = f0.w * s00 + f1.x * s01 + f1.y * s02;
        float p2 = f1.z * s00 + f1.w * s01 + f2.x * s02;
        float p3 = f2.y * s00 + f2.z * s01 + f2.w * s02;
        float q0 = f0.x * s10 + f0.y * s11 + f0.z * s12;
        float q1 = f0.w * s10 + f1.x * s11 + f1.y * s12;
        float q2 = f1.z * s10 + f1.w * s11 + f2.x * s12;
        float q3 = f2.y * s10 + f2.z * s11 + f2.w * s12;
        float d;
        d = xa.x - p0; acc0 = fmaf(d, d, acc0);
        d = xa.y - p1; acc0 = fmaf(d, d, acc0);
        d = xa.z - p2; acc0 = fmaf(d, d, acc0);
        d = xa.w - p3; acc0 = fmaf(d, d, acc0);
        d = xb.x - q0; acc1 = fmaf(d, d, acc1);
        d = xb.y - q1; acc1 = fmaf(d, d, acc1);
        d = xb.z - q2; acc1 = fmaf(d, d, acc1);
        d = xb.w - q3; acc1 = fmaf(d, d, acc1);
    }
#pragma unroll
    for (int o = 16; o; o >>= 1) {
        acc0 += __shfl_down_sync(0xffffffffu, acc0, o);
        acc1 += __shfl_down_sync(0xffffffffu, acc1, o);
    }
    if (lane == 0) {
        g_invw[a0] = 1.0f / acc0;
        g_invw[a1] = 1.0f / acc1;
    }
    __syncthreads();                 // all warps' stores issued
    if (threadIdx.x == 0) {
        __threadfence();             // make g_invw visible device-wide
        atomicAdd(&g_wdone, 1);      // signal this block's completion
    }
}

// ---------------- kernel C: categorical + fused mean-of-gathered ----------
// Round-16 form, with the prologue's 1024 exact logf evals replaced by the
// round-3-validated UPPER-BOUND seeding:
//   real -log(u) <= s + s^2 for u >= 0.34 (tt > 1.34), s = 2-tt exact.
//   thr = min over k=0 of fl(fmaf(s,s,s)*1.00002)*iw, further *1.000004.
// thr >= every ub >= every v >= row min, so the screen's safety proof is
// unchanged (strictly more conservative than the exact-seeded threshold).
// All 8 k-iterations now go through the cheap screen; survivors exact.
__global__ void k_cat(uint32_t kc0, uint32_t kc1, float* __restrict__ out)
{
    const int row = blockIdx.x;
    const int t = threadIdx.x;
    const float INF = __int_as_float(0x7f800000);
    int lane = t & 31, warp = t >> 5;

    __shared__ float shv[8];
    __shared__ int   shi[8];
    __shared__ float sthr;

    const uint32_t base = (uint32_t)row * (uint32_t)NP;

    // ---- Phase A: PRNG only (independent of k_weights output) ----
    uint32_t B[32];
#pragma unroll
    for (int k = 0; k < 8; ++k) {
        uint32_t n0 = base + (uint32_t)((k << 10) + 4 * t);
        B[4 * k + 0] = tf32(kc0, kc1, n0 + 0u);
        B[4 * k + 1] = tf32(kc0, kc1, n0 + 1u);
        B[4 * k + 2] = tf32(kc0, kc1, n0 + 2u);
        B[4 * k + 3] = tf32(kc0, kc1, n0 + 3u);
    }

    // ---- Gate: wait for k_weights' g_invw to be complete & visible ----
    cudaGridDependencySynchronize();          // PDL bookkeeping (cheap)
    if (t == 0) {
        while (atomicAdd(&g_wdone, 0) < NWB)
            __nanosleep(64);
    }
    __syncthreads();
    __threadfence();                          // acquire

    const float4* invw4 = reinterpret_cast<const float4*>(g_invw);

    // ---- prologue: threshold from k=0 UPPER BOUNDS (no logf) ----
    {
        float4 iw = __ldg(invw4 + t);
        float thr_l = INF;
#pragma unroll
        for (int i = 0; i < 4; ++i) {
            uint32_t tb = __umulhi(B[i], 0x00800000u) + 0x3f800000u;
            float tt = __uint_as_float(tb);
            float s  = 2.0f - tt;                    // = 1-u, exact
            float ivw = (i == 0) ? iw.x : (i == 1) ? iw.y : (i == 2) ? iw.z : iw.w;
            float ub = (fmaf(s, s, s) * 1.00002f) * ivw;  // >= true v for u>=.34
            if (tt > 1.34f) thr_l = fminf(thr_l, ub);
        }
#pragma unroll
        for (int o = 16; o; o >>= 1)
            thr_l = fminf(thr_l, __shfl_xor_sync(0xffffffffu, thr_l, o));
        if (lane == 0) shv[warp] = thr_l;
        __syncthreads();
        if (t == 0) {
            float m = shv[0];
#pragma unroll
            for (int wq = 1; wq < 8; ++wq) m = fminf(m, shv[wq]);
            sthr = m * 1.000004f;   // fudged static threshold
        }
        __syncthreads();
    }
    const float thr2 = sthr;
    __syncthreads();   // shv reused below; everyone read sthr

    // ---- main loop: k = 0..7 (ALL elements screened), 1 ballot/group ----
    float mv = INF;
    int   mi = 0;
#pragma unroll 1
    for (int k = 0; k < 8; ++k) {
        int j0 = (k << 10) + 4 * t;
        float4 iw = __ldg(invw4 + (k << 8) + t);
        uint32_t b0 = B[4 * k + 0];
        uint32_t b1 = B[4 * k + 1];
        uint32_t b2 = B[4 * k + 2];
        uint32_t b3 = B[4 * k + 3];

        uint32_t t0 = __umulhi(b0, 0x00800000u) + 0x3f800000u;
        uint32_t t1 = __umulhi(b1, 0x00800000u) + 0x3f800000u;
        uint32_t t2 = __umulhi(b2, 0x00800000u) + 0x3f800000u;
        uint32_t t3 = __umulhi(b3, 0x00800000u) + 0x3f800000u;
        float e0 = (2.0f - __uint_as_float(t0)) * iw.x;   // s = 1-u, exact
        float e1 = (2.0f - __uint_as_float(t1)) * iw.y;
        float e2 = (2.0f - __uint_as_float(t2)) * iw.z;
        float e3 = (2.0f - __uint_as_float(t3)) * iw.w;
        float emin = fminf(fminf(e0, e1), fminf(e2, e3));

        if (__ballot_sync(0xffffffffu, emin <= thr2)) {
            float v0 = exact_v(b0, iw.x);
            if (v0 < mv) { mv = v0; mi = j0; }
            float v1 = exact_v(b1, iw.y);
            if (v1 < mv) { mv = v1; mi = j0 + 1; }
            float v2 = exact_v(b2, iw.z);
            if (v2 < mv) { mv = v2; mi = j0 + 2; }
            float v3 = exact_v(b3, iw.w);
            if (v3 < mv) { mv = v3; mi = j0 + 3; }
        }
    }

    // ---- block argmin reduce (value, then lower index on exact ties) ----
#pragma unroll
    for (int o = 16; o; o >>= 1) {
        float ov = __shfl_down_sync(0xffffffffu, mv, o);
        int   oi = __shfl_down_sync(0xffffffffu, mi, o);
        if (ov < mv || (ov == mv && oi < mi)) { mv = ov; mi = oi; }
    }
    if (lane == 0) { shv[warp] = mv; shi[warp] = mi; }
    __syncthreads();
    if (warp == 0) {
        float v2 = (lane < 8) ? shv[lane] : INF;
        int   i2 = (lane < 8) ? shi[lane] : 0x7fffffff;
#pragma unroll
        for (int o = 4; o; o >>= 1) {
            float ov = __shfl_down_sync(0xffffffffu, v2, o);
            int   oi = __shfl_down_sync(0xffffffffu, i2, o);
            if (ov < v2 || (ov == v2 && oi < i2)) { v2 = ov; i2 = oi; }
        }
        if (lane == 0) {
            atomicAdd(&g_sum[0], g_state[3 * i2 + 0]);
            atomicAdd(&g_sum[1], g_state[3 * i2 + 1]);
            atomicAdd(&g_sum[2], g_state[3 * i2 + 2]);
            __threadfence();
            if (atomicAdd(&g_done, 1) == (int)gridDim.x - 1) {
                out[0] = g_sum[0] * (1.0f / NP);
                out[1] = g_sum[1] * (1.0f / NP);
                out[2] = g_sum[2] * (1.0f / NP);
            }
        }
    }
}

// ---------------- host: key derivation (fold-like split) ------------------
static void h_tf(uint32_t k0, uint32_t k1, uint32_t x0, uint32_t x1,
                 uint32_t& y0, uint32_t& y1)
{
    uint32_t k2 = k0 ^ k1 ^ 0x1BD11BDAu;
    x0 += k0; x1 += k1;
    const int R0[4] = {13, 15, 26, 6}, R1[4] = {17, 29, 16, 24};
    const int* RS[5] = {R0, R1, R0, R1, R0};
    const uint32_t ks[3] = {k0, k1, k2};
    for (int g = 0; g < 5; ++g) {
        for (int q = 0; q < 4; ++q) {
            x0 += x1;
            int r = RS[g][q];
            x1 = (x1 << r) | (x1 >> (32 - r));
            x1 ^= x0;
        }
        x0 += ks[(g + 1) % 3];
        x1 += ks[(g + 2) % 3] + (uint32_t)(g + 1);
    }
    y0 = x0; y1 = x1;
}

extern "C" void kernel_launch(void* const* d_in, const int* in_sizes, int n_in,
                              void* d_out, int out_size)
{
    const float* x  = (const float*)d_in[0];  // inputs (1, C, P)
    const float* sv = (const float*)d_in[1];  // state_vector (P, 3)
    const float* T  = (const float*)d_in[2];  // transition (3, 3)
    const float* Q  = (const float*)d_in[3];  // process noise cov (3, 3)
    const float* F  = (const float*)d_in[4];  // forward_matrix (C, 3)

    uint32_t kn0, kn1, kc0, kc1;
    h_tf(0u, 42u, 0u, 0u, kn0, kn1);  // k_noise
    h_tf(0u, 42u, 0u, 1u, kc0, kc1);  // k_cat

    k_state  <<<NP / 128, 128>>>(sv, T, Q, kn0, kn1);
    k_weights<<<NWB, 256>>>(x, F);

    // k_cat with Programmatic Dependent Launch: Phase A (pure PRNG) overlaps
    // k_weights; the g_wdone flag (not the PDL sync) guards the invw reads.
    cudaLaunchConfig_t cfg = {};
    cfg.gridDim = dim3(NP, 1, 1);
    cfg.blockDim = dim3(256, 1, 1);
    cudaLaunchAttribute attrs[1];
    attrs[0].id = cudaLaunchAttributeProgrammaticStreamSerialization;
    attrs[0].val.programmaticStreamSerializationAllowed = 1;
    cfg.attrs = attrs;
    cfg.numAttrs = 1;
    cudaError_t e = cudaLaunchKernelEx(&cfg, k_cat, kc0, kc1, (float*)d_out);
    if (e != cudaSuccess) {
        // Fallback: plain serialized launch (gate passes immediately).
        k_cat<<<NP, 256>>>(kc0, kc1, (float*)d_out);
    }
}